// round 1
// baseline (speedup 1.0000x reference)
#include <cuda_runtime.h>
#include <math.h>

#define NB 16
#define HW 512
#define NPIX (NB*HW*HW)

// ---------------- device scratch (no allocations allowed) ----------------
__device__ float  g_resp[NB*HW*HW];   // GFTT response, 16 MB
__device__ float  g_bval[NB*4096];    // per-8x8-block NMS max value
__device__ int    g_bpos[NB*4096];    // its position (y*512+x)
__device__ float  g_thr[NB];          // 500th largest block-max per image
__device__ int    g_surv[NB*4096];    // surviving corner pos per block, -1 if none
__device__ double g_pb[4096];         // per-CTA bce partials
__device__ double g_pr[4096];         // per-CTA reg partials

__device__ __forceinline__ int refl512(int i){ return i<0 ? -i : (i>511 ? 1022-i : i); }
__device__ __forceinline__ int clamp512(int i){ return i<0?0:(i>511?511:i); }

__device__ __forceinline__ void gw7(float* w){
  float e0=expf(-4.5f), e1=expf(-2.0f), e2=expf(-0.5f);
  float s=1.0f+2.0f*(e0+e1+e2);
  w[0]=e0/s; w[1]=e1/s; w[2]=e2/s; w[3]=1.0f/s; w[4]=w[2]; w[5]=w[1]; w[6]=w[0];
}

// ---------------- K1: gray -> sobel -> structure tensor -> gauss7 (separable) -> min-eig
__global__ __launch_bounds__(1024) void k_response(const float* __restrict__ imgs){
  const int b = blockIdx.z;
  const int ty0 = blockIdx.y*32, tx0 = blockIdx.x*32;
  __shared__ float sg[40][40];                    // gray, replicate-clamped, halo 4
  __shared__ float p0[38][38], p1[38][38], p2[38][38]; // dx2, dy2, dxy at reflected coords
  __shared__ float t0[38][32], t1[38][32], t2[38][32]; // row-blurred
  const int tid = threadIdx.y*32 + threadIdx.x;
  const float* rr = imgs + (size_t)b*3*HW*HW;
  const float* gg = rr + HW*HW;
  const float* bb = gg + HW*HW;
  for (int i=tid; i<40*40; i+=1024){
    int iy=i/40, ix=i%40;
    int gy=clamp512(ty0-4+iy), gx=clamp512(tx0-4+ix);
    int o=gy*HW+gx;
    sg[iy][ix] = 0.299f*rr[o] + 0.587f*gg[o] + 0.114f*bb[o];
  }
  __syncthreads();
  // products at reflected coordinates (reflect pad of products == products at reflected coords)
  for (int i=tid; i<38*38; i+=1024){
    int iy=i/38, ix=i%38;
    int qy=refl512(ty0-3+iy), qx=refl512(tx0-3+ix);
    int ly=qy-ty0+4, lx=qx-tx0+4;      // stays within [0,40) incl. border reflection
    float a=sg[ly-1][lx-1], b_=sg[ly-1][lx], c=sg[ly-1][lx+1];
    float d=sg[ly][lx-1],                    e=sg[ly][lx+1];
    float f=sg[ly+1][lx-1], h=sg[ly+1][lx], k=sg[ly+1][lx+1];
    float dx=(c-a+2.0f*(e-d)+k-f)*0.125f;
    float dy=(f-a+2.0f*(h-b_)+k-c)*0.125f;
    p0[iy][ix]=dx*dx; p1[iy][ix]=dy*dy; p2[iy][ix]=dx*dy;
  }
  __syncthreads();
  float w[7]; gw7(w);
  // separable gaussian: row pass
  for (int i=tid; i<38*32; i+=1024){
    int iy=i/32, ix=i%32;
    float s0=0.f,s1=0.f,s2=0.f;
    #pragma unroll
    for (int k=0;k<7;k++){
      s0 += w[k]*p0[iy][ix+k];
      s1 += w[k]*p1[iy][ix+k];
      s2 += w[k]*p2[iy][ix+k];
    }
    t0[iy][ix]=s0; t1[iy][ix]=s1; t2[iy][ix]=s2;
  }
  __syncthreads();
  // col pass + min eigenvalue
  const int oy=threadIdx.y, ox=threadIdx.x;
  float b0=0.f,b1=0.f,b2=0.f;
  #pragma unroll
  for (int k=0;k<7;k++){
    b0 += w[k]*t0[oy+k][ox];
    b1 += w[k]*t1[oy+k][ox];
    b2 += w[k]*t2[oy+k][ox];
  }
  float det=b0*b1-b2*b2;
  float tr=b0+b1;
  float resp=0.5f*(tr - sqrtf(fabsf(tr*tr - 4.0f*det)));
  g_resp[((size_t)b*HW + ty0+oy)*HW + tx0+ox] = resp;
}

// ---------------- K2: 5x5 NMS + per-8x8-block max (value + position)
__global__ __launch_bounds__(256) void k_nms(){
  const int b = blockIdx.z;
  const int ty0 = blockIdx.y*16, tx0 = blockIdx.x*16;
  __shared__ float sr[20][20];
  __shared__ float sv[16][16];
  const int tid = threadIdx.y*16 + threadIdx.x;
  const float NEG = __int_as_float(0xff800000u); // -inf
  const float* rp = g_resp + (size_t)b*HW*HW;
  for (int i=tid;i<400;i+=256){
    int iy=i/20, ix=i%20;
    int gy=ty0-2+iy, gx=tx0-2+ix;
    sr[iy][ix] = (gy>=0 && gy<HW && gx>=0 && gx<HW) ? rp[gy*HW+gx] : NEG;
  }
  __syncthreads();
  const int ty=threadIdx.y, tx=threadIdx.x;
  float v = sr[ty+2][tx+2];
  float m = NEG;
  #pragma unroll
  for (int i=0;i<5;i++)
    #pragma unroll
    for (int j=0;j<5;j++) m = fmaxf(m, sr[ty+i][tx+j]);
  sv[ty][tx] = (v==m) ? v : 0.0f;
  __syncthreads();
  if ((ty&7)==0 && (tx&7)==0){
    float bv = sv[ty][tx];
    int   bp = (ty0+ty)*HW + (tx0+tx);
    for (int i=0;i<8;i++)
      for (int j=0;j<8;j++){
        float q = sv[ty+i][tx+j];
        if (q > bv){ bv=q; bp=(ty0+ty+i)*HW + (tx0+tx+j); }
      }
    int bidx = b*4096 + ((ty0+ty)>>3)*64 + ((tx0+tx)>>3);
    g_bval[bidx]=bv; g_bpos[bidx]=bp;
  }
}

// ---------------- K3: per-image bitonic sort of 4096 block maxima -> 500th value
__global__ __launch_bounds__(1024) void k_topk(){
  __shared__ float a[4096];
  const int img = blockIdx.x, tid = threadIdx.x;
  for (int i=tid;i<4096;i+=1024) a[i]=g_bval[img*4096+i];
  __syncthreads();
  for (int k=2;k<=4096;k<<=1){
    for (int j=k>>1;j>0;j>>=1){
      for (int i=tid;i<4096;i+=1024){
        int ixj=i^j;
        if (ixj>i){
          float x=a[i], y=a[ixj];
          bool desc = ((i&k)==0);
          if (desc ? (x<y) : (x>y)){ a[i]=y; a[ixj]=x; }
        }
      }
      __syncthreads();
    }
  }
  if (tid==0) g_thr[img]=a[499];
}

// ---------------- K4: select top-500 + second 5x5 NMS (3x3 block neighborhood)
__global__ __launch_bounds__(1024) void k_sel(){
  int gid = blockIdx.x*1024 + threadIdx.x;
  if (gid >= NB*4096) return;
  int img = gid>>12, bid = gid&4095;
  int by = bid>>6, bx = bid&63;
  float v = g_bval[gid];
  float thr = g_thr[img];
  int surv = -1;
  if (v>0.0f && v>=thr){
    int pos = g_bpos[gid];
    int y = pos>>9, x = pos&511;
    bool ok = true;
    #pragma unroll
    for (int dby=-1;dby<=1;dby++)
      #pragma unroll
      for (int dbx=-1;dbx<=1;dbx++){
        if (dby==0 && dbx==0) continue;
        int nby=by+dby, nbx=bx+dbx;
        if (nby<0||nby>63||nbx<0||nbx>63) continue;
        int ng = img*4096 + nby*64 + nbx;
        float nv = g_bval[ng];
        if (nv>v && nv>=thr){
          int np = g_bpos[ng];
          int ny=np>>9, nx=np&511;
          if (abs(ny-y)<=2 && abs(nx-x)<=2) ok=false;
        }
      }
    surv = ok ? pos : -1;
  }
  g_surv[gid] = surv;
}

// ---------------- K5: fused loss: laplacian + reg + sparse corner blur + bce, per-CTA partials
__global__ __launch_bounds__(1024) void k_loss(const float* __restrict__ scores){
  const int b = blockIdx.z;
  const int ty0 = blockIdx.y*32, tx0 = blockIdx.x*32;
  const int tby = ty0>>3, tbx = tx0>>3;
  __shared__ float sc[36][36];
  __shared__ int   ss[6][6];
  __shared__ float rb[32], rr2[32];
  const int tid = threadIdx.y*32 + threadIdx.x;
  const float* sp = scores + (size_t)b*HW*HW;
  for (int i=tid;i<1296;i+=1024){
    int iy=i/36, ix=i%36;
    sc[iy][ix] = sp[refl512(ty0-2+iy)*HW + refl512(tx0-2+ix)];
  }
  if (tid<36){
    int iy=tid/6, ix=tid%6;
    int by=tby-1+iy, bx=tbx-1+ix;
    ss[iy][ix] = (by>=0 && by<64 && bx>=0 && bx<64) ? g_surv[b*4096+by*64+bx] : -1;
  }
  __syncthreads();
  const int oy=threadIdx.y, ox=threadIdx.x;
  const int y=ty0+oy, x=tx0+ox;
  float p = sc[oy+2][ox+2];
  float S = 0.f;
  #pragma unroll
  for (int i=0;i<5;i++)
    #pragma unroll
    for (int j=0;j<5;j++) S += sc[oy+i][ox+j];
  float lap = (S - 25.0f*p) * (1.0f/48.0f);
  float reg = p * expf(-lap);

  float w[7]; gw7(w);
  float c = 0.0f;
  {
    // a 7-wide window spans at most 2 aligned 8-blocks per dim (reflection stays inside)
    int r0 = (y-3<0?0:y-3)>>3, r1 = (y+3>511?511:y+3)>>3;
    int c0 = (x-3<0?0:x-3)>>3, c1 = (x+3>511?511:x+3)>>3;
    bool any=false;
    for (int br=r0;br<=r1;br++)
      for (int bc=c0;bc<=c1;bc++)
        if (ss[br-tby+1][bc-tbx+1] >= 0) any=true;
    if (any){
      #pragma unroll
      for (int ky=0;ky<7;ky++){
        int yy = refl512(y+ky-3);
        int iy2 = (yy>>3)-tby+1;
        float wy = w[ky];
        #pragma unroll
        for (int kx=0;kx<7;kx++){
          int xx = refl512(x+kx-3);
          int sv = ss[iy2][(xx>>3)-tbx+1];
          if (sv == yy*HW+xx) c += wy*w[kx];
        }
      }
    }
  }
  float logp = fmaxf(logf(p), -100.0f);
  float l1m  = fmaxf(log1pf(-p), -100.0f);
  float bce  = -(c*logp + (1.0f-c)*l1m);

  // deterministic block reduction
  float v1=bce, v2=reg;
  #pragma unroll
  for (int off=16;off;off>>=1){
    v1 += __shfl_down_sync(0xffffffffu, v1, off);
    v2 += __shfl_down_sync(0xffffffffu, v2, off);
  }
  int wid=tid>>5, lane=tid&31;
  if (lane==0){ rb[wid]=v1; rr2[wid]=v2; }
  __syncthreads();
  if (tid<32){
    v1=rb[tid]; v2=rr2[tid];
    #pragma unroll
    for (int off=16;off;off>>=1){
      v1 += __shfl_down_sync(0xffffffffu, v1, off);
      v2 += __shfl_down_sync(0xffffffffu, v2, off);
    }
    if (tid==0){
      int bid = (blockIdx.z*16 + blockIdx.y)*16 + blockIdx.x;
      g_pb[bid]=(double)v1; g_pr[bid]=(double)v2;
    }
  }
}

// ---------------- K6: deterministic final reduction of 4096 partials
__global__ __launch_bounds__(1024) void k_final(float* __restrict__ out){
  __shared__ double sb[1024], sr[1024];
  const int t = threadIdx.x;
  double b=0.0, r=0.0;
  for (int i=t;i<4096;i+=1024){ b += g_pb[i]; r += g_pr[i]; }
  sb[t]=b; sr[t]=r; __syncthreads();
  for (int s=512;s;s>>=1){
    if (t<s){ sb[t]+=sb[t+s]; sr[t]+=sr[t+s]; }
    __syncthreads();
  }
  if (t==0){
    double n = (double)NPIX;
    out[0] = (float)(sb[0]/n + (sr[0]/n)*10.0);
  }
}

// ---------------- launch ----------------
extern "C" void kernel_launch(void* const* d_in, const int* in_sizes, int n_in,
                              void* d_out, int out_size){
  const float* scores = (const float*)d_in[0];
  const float* imgs   = (const float*)d_in[1];
  if (in_sizes[0] != NB*1*HW*HW){ // safety: identify tensors by size
    const float* tmp = scores; scores = imgs; imgs = tmp;
  }
  dim3 blk32(32,32), grd32(16,16,NB);
  k_response<<<grd32, blk32>>>(imgs);
  k_nms<<<dim3(32,32,NB), dim3(16,16)>>>();
  k_topk<<<NB, 1024>>>();
  k_sel<<<(NB*4096+1023)/1024, 1024>>>();
  k_loss<<<grd32, blk32>>>(scores);
  k_final<<<1, 1024>>>((float*)d_out);
}

// round 2
// speedup vs baseline: 1.1796x; 1.1796x over previous
#include <cuda_runtime.h>
#include <math.h>

#define NB 16
#define HW 512
#define NPIX (NB*HW*HW)

// ---------------- device scratch ----------------
__device__ float  g_bval[NB*4096];    // per-8x8-block NMS max value
__device__ int    g_bpos[NB*4096];    // its position (y*512+x)
__device__ int    g_surv[NB*4096];    // surviving corner pos per block, -1 if none
__device__ double g_pb[4096];         // per-CTA base-bce partials
__device__ double g_pr[4096];         // per-CTA reg partials
__device__ double g_pc[NB];           // per-image corner bce correction

__device__ __forceinline__ int refl512(int i){ return i<0 ? -i : (i>511 ? 1022-i : i); }
__device__ __forceinline__ int clamp512(int i){ return i<0?0:(i>511?511:i); }

__device__ __forceinline__ void gw7(float* w){
  float e0=expf(-4.5f), e1=expf(-2.0f), e2=expf(-0.5f);
  float s=1.0f+2.0f*(e0+e1+e2);
  w[0]=e0/s; w[1]=e1/s; w[2]=e2/s; w[3]=1.0f/s; w[4]=w[2]; w[5]=w[1]; w[6]=w[0];
}

// ============ K1: fused gray->sobel->struct tensor->gauss7->min-eig->NMS->blockmax ============
// Output tile 32x32 (NMS). Response needed on tile+-2 (36x36), products on +-3 more (42x42),
// gray on +-1 more (44x44). Single aliased smem buffer, 47056 B (static-smem legal).
__global__ __launch_bounds__(1024) void k1(const float* __restrict__ imgs){
  const int b = blockIdx.z;
  const int ty0 = blockIdx.y*32, tx0 = blockIdx.x*32;
  __shared__ float buf[11764];
  float* p0 = buf;          // 42x42 = 1764
  float* p1 = buf + 1764;
  float* p2 = buf + 3528;
  float* t0 = buf + 5292;   // 42x36 = 1512
  float* t1 = buf + 6804;
  float* t2 = buf + 8316;
  float* sg = buf + 9828;   // 44x44 = 1936 (dead after stage B)
  float* resp = buf + 9828; // 36x36 = 1296 (aliases sg)
  float* sv   = buf;        // 32x32 = 1024 (aliases p0, dead after stage C)
  const int tid = threadIdx.y*32 + threadIdx.x;
  const float NEG = __int_as_float(0xff800000u);

  const float* rr = imgs + (size_t)b*3*HW*HW;
  const float* gg = rr + HW*HW;
  const float* bb = gg + HW*HW;

  // A: gray with replicate clamp, 44x44
  for (int i=tid; i<1936; i+=1024){
    int iy=i/44, ix=i%44;
    int gy=clamp512(ty0-6+iy), gx=clamp512(tx0-6+ix);
    int o=gy*HW+gx;
    sg[i] = 0.299f*rr[o] + 0.587f*gg[o] + 0.114f*bb[o];
  }
  __syncthreads();

  // B: gradient products at reflected coords, 42x42
  for (int i=tid; i<1764; i+=1024){
    int iy=i/42, ix=i%42;
    int qy=refl512(ty0-5+iy), qx=refl512(tx0-5+ix);
    int ly=qy-ty0+6, lx=qx-tx0+6;
    const float* c0=&sg[(ly-1)*44+lx];
    const float* c1=&sg[ ly   *44+lx];
    const float* c2=&sg[(ly+1)*44+lx];
    float a=c0[-1], b_=c0[0], c=c0[1];
    float d=c1[-1],            e=c1[1];
    float f=c2[-1], h=c2[0],  k=c2[1];
    float dx=(c-a+2.0f*(e-d)+k-f)*0.125f;
    float dy=(f-a+2.0f*(h-b_)+k-c)*0.125f;
    p0[i]=dx*dx; p1[i]=dy*dy; p2[i]=dx*dy;
  }
  __syncthreads();

  float w[7]; gw7(w);

  // C: separable gaussian row pass, 42 rows x 36 cols
  for (int i=tid; i<1512; i+=1024){
    int iy=i/36, ox=i%36;
    int base=iy*42+ox;
    float s0=0.f,s1=0.f,s2=0.f;
    #pragma unroll
    for (int k=0;k<7;k++){
      s0 += w[k]*p0[base+k];
      s1 += w[k]*p1[base+k];
      s2 += w[k]*p2[base+k];
    }
    t0[i]=s0; t1[i]=s1; t2[i]=s2;
  }
  __syncthreads();

  // D: col pass + min eigenvalue, 36x36; out-of-image -> -inf for NMS
  for (int i=tid; i<1296; i+=1024){
    int oy=i/36, ox=i%36;
    float b0=0.f,b1=0.f,b2=0.f;
    #pragma unroll
    for (int k=0;k<7;k++){
      int o=(oy+k)*36+ox;
      b0 += w[k]*t0[o];
      b1 += w[k]*t1[o];
      b2 += w[k]*t2[o];
    }
    float det=b0*b1-b2*b2;
    float tr=b0+b1;
    float r=0.5f*(tr - sqrtf(fabsf(tr*tr - 4.0f*det)));
    int ry=ty0-2+oy, rx=tx0-2+ox;
    resp[i] = (ry>=0 && ry<HW && rx>=0 && rx<HW) ? r : NEG;
  }
  __syncthreads();

  // E: 5x5 NMS + per-8x8-block max
  const int oy=threadIdx.y, ox=threadIdx.x;
  {
    float v = resp[(oy+2)*36 + ox+2];
    float m = NEG;
    #pragma unroll
    for (int i=0;i<5;i++)
      #pragma unroll
      for (int j=0;j<5;j++) m = fmaxf(m, resp[(oy+i)*36 + ox+j]);
    sv[oy*32+ox] = (v==m) ? v : 0.0f;
  }
  __syncthreads();
  if ((oy&7)==0 && (ox&7)==0){
    float bv = sv[oy*32+ox];
    int   bp = (ty0+oy)*HW + (tx0+ox);
    for (int i=0;i<8;i++)
      for (int j=0;j<8;j++){
        float q = sv[(oy+i)*32 + ox+j];
        if (q > bv){ bv=q; bp=(ty0+oy+i)*HW + (tx0+ox+j); }
      }
    int bidx = b*4096 + ((ty0+oy)>>3)*64 + ((tx0+ox)>>3);
    g_bval[bidx]=bv; g_bpos[bidx]=bp;
  }
}

// ============ K2: per-image radix-select (500th largest) + top-k select + second NMS ============
__global__ __launch_bounds__(1024) void k2(){
  const int img = blockIdx.x, tid = threadIdx.x;
  __shared__ float fv[4096];
  __shared__ int   pos[4096];
  __shared__ unsigned hist[256];
  __shared__ unsigned s_prefix;
  __shared__ int s_k;
  for (int i=tid;i<4096;i+=1024){
    fv[i]=g_bval[img*4096+i];
    pos[i]=g_bpos[img*4096+i];
  }
  if (tid==0){ s_prefix=0u; s_k=500; }
  __syncthreads();

  // 4 x 8-bit MSB-first radix select: exact 500th-largest bit pattern
  for (int pass=0; pass<4; pass++){
    int shift = 24 - 8*pass;
    unsigned hi_mask = (pass==0) ? 0u : (0xFFFFFFFFu << (shift+8));
    if (tid < 256) hist[tid]=0u;
    __syncthreads();
    unsigned prefix = s_prefix;
    for (int i=tid;i<4096;i+=1024){
      unsigned bits = __float_as_uint(fv[i]);
      unsigned u = (bits & 0x80000000u) ? ~bits : (bits | 0x80000000u);
      if ((u & hi_mask) == prefix) atomicAdd(&hist[(u>>shift)&255u], 1u);
    }
    __syncthreads();
    if (tid==0){
      int k = s_k; unsigned cum=0u; int d=255;
      for (; d>0; d--){
        unsigned h = hist[d];
        if (cum + h >= (unsigned)k) break;
        cum += h;
      }
      s_k = k - (int)cum;
      s_prefix = prefix | ((unsigned)d << shift);
    }
    __syncthreads();
  }
  unsigned u = s_prefix;
  unsigned tbits = (u & 0x80000000u) ? (u ^ 0x80000000u) : ~u;
  float thr = __uint_as_float(tbits);

  // select + 3x3-block-neighborhood second NMS (in smem)
  for (int i=tid;i<4096;i+=1024){
    float v = fv[i];
    int surv = -1;
    if (v>0.0f && v>=thr){
      int by=i>>6, bx=i&63;
      int p = pos[i];
      int y=p>>9, x=p&511;
      bool ok = true;
      #pragma unroll
      for (int dby=-1;dby<=1;dby++)
        #pragma unroll
        for (int dbx=-1;dbx<=1;dbx++){
          if (dby==0 && dbx==0) continue;
          int nby=by+dby, nbx=bx+dbx;
          if (nby<0||nby>63||nbx<0||nbx>63) continue;
          int n = nby*64+nbx;
          float nv = fv[n];
          if (nv>v && nv>=thr){
            int np = pos[n];
            int ny=np>>9, nx=np&511;
            if (abs(ny-y)<=2 && abs(nx-x)<=2) ok=false;
          }
        }
      surv = ok ? p : -1;
    }
    g_surv[img*4096+i] = surv;
  }
}

// ============ K3: laplacian + reg + base bce (no corner gather), separable 5x5 box ============
__global__ __launch_bounds__(1024) void k3(const float* __restrict__ scores){
  const int b = blockIdx.z;
  const int ty0 = blockIdx.y*32, tx0 = blockIdx.x*32;
  __shared__ float sc[36*36];
  __shared__ float rs[36*32];
  __shared__ float rb[32], rr2[32];
  const int tid = threadIdx.y*32 + threadIdx.x;
  const float* sp = scores + (size_t)b*HW*HW;
  for (int i=tid;i<1296;i+=1024){
    int iy=i/36, ix=i%36;
    sc[i] = sp[refl512(ty0-2+iy)*HW + refl512(tx0-2+ix)];
  }
  __syncthreads();
  // row sums of 5
  for (int i=tid;i<36*32;i+=1024){
    int iy=i/32, ox=i%32;
    int base=iy*36+ox;
    rs[i] = sc[base]+sc[base+1]+sc[base+2]+sc[base+3]+sc[base+4];
  }
  __syncthreads();
  const int oy=threadIdx.y, ox=threadIdx.x;
  float S = rs[oy*32+ox]+rs[(oy+1)*32+ox]+rs[(oy+2)*32+ox]+rs[(oy+3)*32+ox]+rs[(oy+4)*32+ox];
  float p = sc[(oy+2)*36 + ox+2];
  float lap = (S - 25.0f*p) * (1.0f/48.0f);
  float reg = p * expf(-lap);
  float bce0 = -fmaxf(log1pf(-p), -100.0f);

  float v1=bce0, v2=reg;
  #pragma unroll
  for (int off=16;off;off>>=1){
    v1 += __shfl_down_sync(0xffffffffu, v1, off);
    v2 += __shfl_down_sync(0xffffffffu, v2, off);
  }
  int wid=tid>>5, lane=tid&31;
  if (lane==0){ rb[wid]=v1; rr2[wid]=v2; }
  __syncthreads();
  if (tid<32){
    v1=rb[tid]; v2=rr2[tid];
    #pragma unroll
    for (int off=16;off;off>>=1){
      v1 += __shfl_down_sync(0xffffffffu, v1, off);
      v2 += __shfl_down_sync(0xffffffffu, v2, off);
    }
    if (tid==0){
      int bid = (blockIdx.z*16 + blockIdx.y)*16 + blockIdx.x;
      g_pb[bid]=(double)v1; g_pr[bid]=(double)v2;
    }
  }
}

// ============ K4: per-survivor 7x7 gaussian correction: sum w*(logp - log1mp) ============
__global__ __launch_bounds__(1024) void k4(const float* __restrict__ scores){
  const int img = blockIdx.x, tid = threadIdx.x;
  __shared__ float rsh[32];
  const float* sp = scores + (size_t)img*HW*HW;
  float w[7]; gw7(w);
  float acc = 0.0f;
  for (int i=tid;i<4096;i+=1024){
    int s = g_surv[img*4096+i];
    if (s < 0) continue;
    int y=s>>9, x=s&511;
    #pragma unroll
    for (int ky=0;ky<7;ky++){
      int yy = refl512(y+ky-3);
      float wy = w[ky];
      #pragma unroll
      for (int kx=0;kx<7;kx++){
        int xx = refl512(x+kx-3);
        float p = sp[yy*HW+xx];
        float lp = fmaxf(logf(p), -100.0f);
        float l1 = fmaxf(log1pf(-p), -100.0f);
        acc += wy*w[kx]*(lp - l1);
      }
    }
  }
  #pragma unroll
  for (int off=16;off;off>>=1) acc += __shfl_down_sync(0xffffffffu, acc, off);
  int wid=tid>>5, lane=tid&31;
  if (lane==0) rsh[wid]=acc;
  __syncthreads();
  if (tid<32){
    float v=rsh[tid];
    #pragma unroll
    for (int off=16;off;off>>=1) v += __shfl_down_sync(0xffffffffu, v, off);
    if (tid==0) g_pc[img] = (double)v;
  }
}

// ============ K5: deterministic final reduction ============
__global__ __launch_bounds__(1024) void k5(float* __restrict__ out){
  __shared__ double sb[1024], sr[1024];
  const int t = threadIdx.x;
  double b=0.0, r=0.0;
  for (int i=t;i<4096;i+=1024){ b += g_pb[i]; r += g_pr[i]; }
  sb[t]=b; sr[t]=r; __syncthreads();
  for (int s=512;s;s>>=1){
    if (t<s){ sb[t]+=sb[t+s]; sr[t]+=sr[t+s]; }
    __syncthreads();
  }
  if (t==0){
    double c=0.0;
    for (int i=0;i<NB;i++) c += g_pc[i];
    double n = (double)NPIX;
    out[0] = (float)((sb[0]-c)/n + (sr[0]/n)*10.0);
  }
}

// ---------------- launch ----------------
extern "C" void kernel_launch(void* const* d_in, const int* in_sizes, int n_in,
                              void* d_out, int out_size){
  const float* scores = (const float*)d_in[0];
  const float* imgs   = (const float*)d_in[1];
  if (in_sizes[0] != NB*1*HW*HW){
    const float* tmp = scores; scores = imgs; imgs = tmp;
  }
  dim3 blk(32,32), grd(16,16,NB);
  k1<<<grd, blk>>>(imgs);
  k2<<<NB, 1024>>>();
  k3<<<grd, blk>>>(scores);
  k4<<<NB, 1024>>>(scores);
  k5<<<1, 1024>>>((float*)d_out);
}

// round 4
// speedup vs baseline: 1.2549x; 1.0639x over previous
#include <cuda_runtime.h>
#include <math.h>

#define NB 16
#define HW 512
#define NPIX (NB*HW*HW)

// ---------------- device scratch ----------------
__device__ float  g_bval[NB*4096];    // per-8x8-block NMS max value
__device__ int    g_bpos[NB*4096];    // its position (y*512+x)
__device__ int    g_surv[NB*4096];    // surviving corner pos per block, -1 if none
__device__ float  g_corr[NB*4096];    // per-slot corner bce correction
__device__ double g_pb[4096];         // per-CTA base-bce partials
__device__ double g_pr[4096];         // per-CTA reg partials

__device__ __forceinline__ int refl512(int i){ return i<0 ? -i : (i>511 ? 1022-i : i); }
__device__ __forceinline__ int clamp512(int i){ return i<0?0:(i>511?511:i); }

__device__ __forceinline__ void gw7(float* w){
  float e0=expf(-4.5f), e1=expf(-2.0f), e2=expf(-0.5f);
  float s=1.0f+2.0f*(e0+e1+e2);
  w[0]=e0/s; w[1]=e1/s; w[2]=e2/s; w[3]=1.0f/s; w[4]=w[2]; w[5]=w[1]; w[6]=w[0];
}

// ============ K1: fused gray->sobel->struct tensor->gauss7->min-eig->NMS->blockmax ============
__global__ __launch_bounds__(1024) void k1(const float* __restrict__ imgs){
  const int b = blockIdx.z;
  const int ty0 = blockIdx.y*32, tx0 = blockIdx.x*32;
  __shared__ float buf[11764];
  float* p0 = buf;          // 42x42 = 1764
  float* p1 = buf + 1764;
  float* p2 = buf + 3528;
  float* t0 = buf + 5292;   // 42x36 = 1512
  float* t1 = buf + 6804;
  float* t2 = buf + 8316;
  float* sg = buf + 9828;   // 44x44 = 1936 (dead after stage B)
  float* resp = buf + 9828; // 36x36 = 1296 (aliases sg)
  float* sv   = buf;        // 32x32 = 1024 (aliases p0, dead after stage C)
  const int tid = threadIdx.y*32 + threadIdx.x;
  const float NEG = __int_as_float(0xff800000u);

  const float* rr = imgs + (size_t)b*3*HW*HW;
  const float* gg = rr + HW*HW;
  const float* bb = gg + HW*HW;

  // A: gray with replicate clamp, 44x44
  for (int i=tid; i<1936; i+=1024){
    int iy=i/44, ix=i%44;
    int gy=clamp512(ty0-6+iy), gx=clamp512(tx0-6+ix);
    int o=gy*HW+gx;
    sg[i] = 0.299f*rr[o] + 0.587f*gg[o] + 0.114f*bb[o];
  }
  __syncthreads();

  // B: gradient products at reflected coords, 42x42
  for (int i=tid; i<1764; i+=1024){
    int iy=i/42, ix=i%42;
    int qy=refl512(ty0-5+iy), qx=refl512(tx0-5+ix);
    int ly=qy-ty0+6, lx=qx-tx0+6;
    const float* c0=&sg[(ly-1)*44+lx];
    const float* c1=&sg[ ly   *44+lx];
    const float* c2=&sg[(ly+1)*44+lx];
    float a=c0[-1], b_=c0[0], c=c0[1];
    float d=c1[-1],            e=c1[1];
    float f=c2[-1], h=c2[0],  k=c2[1];
    float dx=(c-a+2.0f*(e-d)+k-f)*0.125f;
    float dy=(f-a+2.0f*(h-b_)+k-c)*0.125f;
    p0[i]=dx*dx; p1[i]=dy*dy; p2[i]=dx*dy;
  }
  __syncthreads();

  float w[7]; gw7(w);

  // C: separable gaussian row pass, 42 rows x 36 cols
  for (int i=tid; i<1512; i+=1024){
    int iy=i/36, ox=i%36;
    int base=iy*42+ox;
    float s0=0.f,s1=0.f,s2=0.f;
    #pragma unroll
    for (int k=0;k<7;k++){
      s0 += w[k]*p0[base+k];
      s1 += w[k]*p1[base+k];
      s2 += w[k]*p2[base+k];
    }
    t0[i]=s0; t1[i]=s1; t2[i]=s2;
  }
  __syncthreads();

  // D: col pass + min eigenvalue, 36x36; out-of-image -> -inf for NMS
  for (int i=tid; i<1296; i+=1024){
    int oy=i/36, ox=i%36;
    float b0=0.f,b1=0.f,b2=0.f;
    #pragma unroll
    for (int k=0;k<7;k++){
      int o=(oy+k)*36+ox;
      b0 += w[k]*t0[o];
      b1 += w[k]*t1[o];
      b2 += w[k]*t2[o];
    }
    float det=b0*b1-b2*b2;
    float tr=b0+b1;
    float r=0.5f*(tr - sqrtf(fabsf(tr*tr - 4.0f*det)));
    int ry=ty0-2+oy, rx=tx0-2+ox;
    resp[i] = (ry>=0 && ry<HW && rx>=0 && rx<HW) ? r : NEG;
  }
  __syncthreads();

  // E: 5x5 NMS + per-8x8-block max
  const int oy=threadIdx.y, ox=threadIdx.x;
  {
    float v = resp[(oy+2)*36 + ox+2];
    float m = NEG;
    #pragma unroll
    for (int i=0;i<5;i++)
      #pragma unroll
      for (int j=0;j<5;j++) m = fmaxf(m, resp[(oy+i)*36 + ox+j]);
    sv[oy*32+ox] = (v==m) ? v : 0.0f;
  }
  __syncthreads();
  if ((oy&7)==0 && (ox&7)==0){
    float bv = sv[oy*32+ox];
    int   bp = (ty0+oy)*HW + (tx0+ox);
    for (int i=0;i<8;i++)
      for (int j=0;j<8;j++){
        float q = sv[(oy+i)*32 + ox+j];
        if (q > bv){ bv=q; bp=(ty0+oy+i)*HW + (tx0+ox+j); }
      }
    int bidx = b*4096 + ((ty0+oy)>>3)*64 + ((tx0+ox)>>3);
    g_bval[bidx]=bv; g_bpos[bidx]=bp;
  }
}

// ============ K2: per-image radix-select (500th largest) + select + second NMS ============
__global__ __launch_bounds__(1024) void k2(){
  const int img = blockIdx.x, tid = threadIdx.x;
  __shared__ float fv[4096];
  __shared__ int   pos[4096];
  __shared__ unsigned hist[256];
  __shared__ unsigned s_prefix;
  __shared__ int s_k;
  for (int i=tid;i<4096;i+=1024){
    fv[i]=g_bval[img*4096+i];
    pos[i]=g_bpos[img*4096+i];
  }
  if (tid==0){ s_prefix=0u; s_k=500; }
  __syncthreads();

  for (int pass=0; pass<4; pass++){
    int shift = 24 - 8*pass;
    unsigned hi_mask = (pass==0) ? 0u : (0xFFFFFFFFu << (shift+8));
    if (tid < 256) hist[tid]=0u;
    __syncthreads();
    unsigned prefix = s_prefix;
    for (int i=tid;i<4096;i+=1024){
      unsigned bits = __float_as_uint(fv[i]);
      unsigned u = (bits & 0x80000000u) ? ~bits : (bits | 0x80000000u);
      if ((u & hi_mask) == prefix) atomicAdd(&hist[(u>>shift)&255u], 1u);
    }
    __syncthreads();
    if (tid==0){
      int k = s_k; unsigned cum=0u; int d=255;
      for (; d>0; d--){
        unsigned h = hist[d];
        if (cum + h >= (unsigned)k) break;
        cum += h;
      }
      s_k = k - (int)cum;
      s_prefix = prefix | ((unsigned)d << shift);
    }
    __syncthreads();
  }
  unsigned u = s_prefix;
  unsigned tbits = (u & 0x80000000u) ? (u ^ 0x80000000u) : ~u;
  float thr = __uint_as_float(tbits);

  for (int i=tid;i<4096;i+=1024){
    float v = fv[i];
    int surv = -1;
    if (v>0.0f && v>=thr){
      int by=i>>6, bx=i&63;
      int p = pos[i];
      int y=p>>9, x=p&511;
      bool ok = true;
      #pragma unroll
      for (int dby=-1;dby<=1;dby++)
        #pragma unroll
        for (int dbx=-1;dbx<=1;dbx++){
          if (dby==0 && dbx==0) continue;
          int nby=by+dby, nbx=bx+dbx;
          if (nby<0||nby>63||nbx<0||nbx>63) continue;
          int n = nby*64+nbx;
          float nv = fv[n];
          if (nv>v && nv>=thr){
            int np = pos[n];
            int ny=np>>9, nx=np&511;
            if (abs(ny-y)<=2 && abs(nx-x)<=2) ok=false;
          }
        }
      surv = ok ? p : -1;
    }
    g_surv[img*4096+i] = surv;
  }
}

// ============ K3: laplacian + reg + base bce, separable 5x5 box ============
__global__ __launch_bounds__(1024) void k3(const float* __restrict__ scores){
  const int b = blockIdx.z;
  const int ty0 = blockIdx.y*32, tx0 = blockIdx.x*32;
  __shared__ float sc[36*36];
  __shared__ float rs[36*32];
  __shared__ float rb[32], rr2[32];
  const int tid = threadIdx.y*32 + threadIdx.x;
  const float* sp = scores + (size_t)b*HW*HW;
  for (int i=tid;i<1296;i+=1024){
    int iy=i/36, ix=i%36;
    sc[i] = sp[refl512(ty0-2+iy)*HW + refl512(tx0-2+ix)];
  }
  __syncthreads();
  for (int i=tid;i<36*32;i+=1024){
    int iy=i/32, ox=i%32;
    int base=iy*36+ox;
    rs[i] = sc[base]+sc[base+1]+sc[base+2]+sc[base+3]+sc[base+4];
  }
  __syncthreads();
  const int oy=threadIdx.y, ox=threadIdx.x;
  float S = rs[oy*32+ox]+rs[(oy+1)*32+ox]+rs[(oy+2)*32+ox]+rs[(oy+3)*32+ox]+rs[(oy+4)*32+ox];
  float p = sc[(oy+2)*36 + ox+2];
  float lap = (S - 25.0f*p) * (1.0f/48.0f);
  float reg = p * expf(-lap);
  float bce0 = -fmaxf(log1pf(-p), -100.0f);

  float v1=bce0, v2=reg;
  #pragma unroll
  for (int off=16;off;off>>=1){
    v1 += __shfl_down_sync(0xffffffffu, v1, off);
    v2 += __shfl_down_sync(0xffffffffu, v2, off);
  }
  int wid=tid>>5, lane=tid&31;
  if (lane==0){ rb[wid]=v1; rr2[wid]=v2; }
  __syncthreads();
  if (tid<32){
    v1=rb[tid]; v2=rr2[tid];
    #pragma unroll
    for (int off=16;off;off>>=1){
      v1 += __shfl_down_sync(0xffffffffu, v1, off);
      v2 += __shfl_down_sync(0xffffffffu, v2, off);
    }
    if (tid==0){
      int bid = (blockIdx.z*16 + blockIdx.y)*16 + blockIdx.x;
      g_pb[bid]=(double)v1; g_pr[bid]=(double)v2;
    }
  }
}

// ============ K4: one warp per slot, lanes cover the 7x7 taps ============
__global__ __launch_bounds__(256) void k4(const float* __restrict__ scores){
  const int wglob = (blockIdx.x*256 + threadIdx.x) >> 5;
  const int lane = threadIdx.x & 31;
  if (wglob >= NB*4096) return;
  const int img = wglob >> 12;
  const int s = g_surv[wglob];
  float acc = 0.0f;
  if (s >= 0){
    const float* sp = scores + (size_t)img*HW*HW;
    float w[7]; gw7(w);
    const int y = s>>9, x = s&511;
    #pragma unroll
    for (int t=lane; t<49; t+=32){
      int ky=t/7, kx=t-ky*7;
      int yy = refl512(y+ky-3);
      int xx = refl512(x+kx-3);
      float p = sp[yy*HW+xx];
      float lp = fmaxf(logf(p), -100.0f);
      float l1 = fmaxf(log1pf(-p), -100.0f);
      acc += w[ky]*w[kx]*(lp - l1);
    }
  }
  #pragma unroll
  for (int off=16;off;off>>=1) acc += __shfl_down_sync(0xffffffffu, acc, off);
  if (lane==0) g_corr[wglob] = acc;
}

// ============ K5: deterministic final reduction ============
__global__ __launch_bounds__(1024) void k5(float* __restrict__ out){
  __shared__ double sb[1024], sr[1024], sx[1024];
  const int t = threadIdx.x;
  double b=0.0, r=0.0, c=0.0;
  for (int i=t;i<4096;i+=1024){ b += g_pb[i]; r += g_pr[i]; }
  for (int i=t;i<NB*4096;i+=1024) c += (double)g_corr[i];
  sb[t]=b; sr[t]=r; sx[t]=c; __syncthreads();
  for (int s=512;s;s>>=1){
    if (t<s){ sb[t]+=sb[t+s]; sr[t]+=sr[t+s]; sx[t]+=sx[t+s]; }
    __syncthreads();
  }
  if (t==0){
    double n = (double)NPIX;
    out[0] = (float)((sb[0]-sx[0])/n + (sr[0]/n)*10.0);
  }
}

// ---------------- launch ----------------
extern "C" void kernel_launch(void* const* d_in, const int* in_sizes, int n_in,
                              void* d_out, int out_size){
  const float* scores = (const float*)d_in[0];
  const float* imgs   = (const float*)d_in[1];
  if (in_sizes[0] != NB*1*HW*HW){
    const float* tmp = scores; scores = imgs; imgs = tmp;
  }
  dim3 blk(32,32), grd(16,16,NB);
  k1<<<grd, blk>>>(imgs);
  k2<<<NB, 1024>>>();
  k3<<<grd, blk>>>(scores);
  k4<<<(NB*4096*32 + 255)/256, 256>>>(scores);
  k5<<<1, 1024>>>((float*)d_out);
}

// round 5
// speedup vs baseline: 1.7365x; 1.3837x over previous
#include <cuda_runtime.h>
#include <math.h>

#define NB 16
#define HW 512
#define NPIX (NB*HW*HW)
#define LCAP 768

// ---------------- device scratch ----------------
__device__ float  g_bval[NB*4096];    // per-8x8-block NMS max value
__device__ int    g_bpos[NB*4096];    // its position (y*512+x)
__device__ int    g_list[NB*LCAP];    // compacted survivor positions
__device__ int    g_cnt[NB];          // survivor count per image
__device__ float  g_corr[NB*LCAP];    // per-survivor-slot bce correction
__device__ double g_pb[4096];         // per-CTA base-bce partials
__device__ double g_pr[4096];         // per-CTA reg partials

__device__ __forceinline__ int refl512(int i){ return i<0 ? -i : (i>511 ? 1022-i : i); }
__device__ __forceinline__ int clamp512(int i){ return i<0?0:(i>511?511:i); }

__device__ __forceinline__ void gw7(float* w){
  float e0=expf(-4.5f), e1=expf(-2.0f), e2=expf(-0.5f);
  float s=1.0f+2.0f*(e0+e1+e2);
  w[0]=e0/s; w[1]=e1/s; w[2]=e2/s; w[3]=1.0f/s; w[4]=w[2]; w[5]=w[1]; w[6]=w[0];
}

// ============ KMAIN: [scores laplacian/bce/reg] + [gray->sobel->ST->gauss7->mineig->NMS->blockmax] ============
__global__ __launch_bounds__(1024) void kmain(const float* __restrict__ imgs,
                                              const float* __restrict__ scores){
  const int b = blockIdx.z;
  const int ty0 = blockIdx.y*32, tx0 = blockIdx.x*32;
  __shared__ __align__(16) float buf[11764];
  const int tid = threadIdx.y*32 + threadIdx.x;
  const int oy = threadIdx.y, ox = threadIdx.x;
  const float NEG = __int_as_float(0xff800000u);

  // ---------- phase 0: scores tile -> laplacian + reg + base bce ----------
  {
    float* sc = buf;            // 36x36 = 1296
    float* rs = buf + 1296;     // 36x32 = 1152
    float* rb = buf + 2448;     // 32
    float* rr2= buf + 2480;     // 32
    const float* sp = scores + (size_t)b*HW*HW;
    for (int i=tid;i<1296;i+=1024){
      int iy=i/36, ix=i%36;
      sc[i] = sp[refl512(ty0-2+iy)*HW + refl512(tx0-2+ix)];
    }
    __syncthreads();
    for (int i=tid;i<1152;i+=1024){
      int iy=i/32, x=i%32;
      int base=iy*36+x;
      rs[i] = sc[base]+sc[base+1]+sc[base+2]+sc[base+3]+sc[base+4];
    }
    __syncthreads();
    float S = rs[oy*32+ox]+rs[(oy+1)*32+ox]+rs[(oy+2)*32+ox]+rs[(oy+3)*32+ox]+rs[(oy+4)*32+ox];
    float p = sc[(oy+2)*36 + ox+2];
    float lap = (S - 25.0f*p) * (1.0f/48.0f);
    float reg = p * expf(-lap);
    float bce0 = -fmaxf(log1pf(-p), -100.0f);
    float v1=bce0, v2=reg;
    #pragma unroll
    for (int off=16;off;off>>=1){
      v1 += __shfl_down_sync(0xffffffffu, v1, off);
      v2 += __shfl_down_sync(0xffffffffu, v2, off);
    }
    if ((tid&31)==0){ rb[tid>>5]=v1; rr2[tid>>5]=v2; }
    __syncthreads();
    // final reduce happens inside stage A (before its barrier)
    if (tid<32){
      float a1=rb[tid], a2=rr2[tid];
      #pragma unroll
      for (int off=16;off;off>>=1){
        a1 += __shfl_down_sync(0xffffffffu, a1, off);
        a2 += __shfl_down_sync(0xffffffffu, a2, off);
      }
      if (tid==0){
        int bid = (blockIdx.z*16 + blockIdx.y)*16 + blockIdx.x;
        g_pb[bid]=(double)a1; g_pr[bid]=(double)a2;
      }
    }
  }

  // ---------- GFTT pipeline ----------
  float2* p01 = (float2*)buf;          // 42x42 float2 = [0, 3528) floats
  float*  p2  = buf + 3528;            // 42x42        = [3528, 5292)
  float2* t01 = (float2*)(buf + 5292); // 42x36 float2 = [5292, 8316)
  float*  t2  = buf + 8316;            // 42x36        = [8316, 9828)
  float*  sg  = buf + 9828;            // 44x44 = 1936
  float*  resp= buf + 9828;            // 36x36 (aliases sg, after B)
  float*  rm  = buf;                   // 36x32 rowmax (aliases p01, after C)
  float*  sv  = buf + 1152;            // 32x32        (aliases p01)

  const float* rr = imgs + (size_t)b*3*HW*HW;
  const float* gg = rr + HW*HW;
  const float* bb = gg + HW*HW;

  // A: gray with replicate clamp, 44x44 (also serves as barrier for phase0 smem)
  for (int i=tid; i<1936; i+=1024){
    int iy=i/44, ix=i%44;
    int gy=clamp512(ty0-6+iy), gx=clamp512(tx0-6+ix);
    int o=gy*HW+gx;
    sg[i] = 0.299f*rr[o] + 0.587f*gg[o] + 0.114f*bb[o];
  }
  __syncthreads();

  // B: gradient products at reflected coords, 42x42
  for (int i=tid; i<1764; i+=1024){
    int iy=i/42, ix=i%42;
    int qy=refl512(ty0-5+iy), qx=refl512(tx0-5+ix);
    int ly=qy-ty0+6, lx=qx-tx0+6;
    const float* c0=&sg[(ly-1)*44+lx];
    const float* c1=&sg[ ly   *44+lx];
    const float* c2=&sg[(ly+1)*44+lx];
    float a=c0[-1], b_=c0[0], c=c0[1];
    float d=c1[-1],            e=c1[1];
    float f=c2[-1], h=c2[0],  k=c2[1];
    float dx=(c-a+2.0f*(e-d)+k-f)*0.125f;
    float dy=(f-a+2.0f*(h-b_)+k-c)*0.125f;
    p01[i] = make_float2(dx*dx, dy*dy);
    p2[i]  = dx*dy;
  }
  __syncthreads();

  float w[7]; gw7(w);

  // C: separable gaussian row pass, 42 rows x 36 cols
  for (int i=tid; i<1512; i+=1024){
    int iy=i/36, x=i%36;
    int base=iy*42+x;
    float s0=0.f,s1=0.f,s2=0.f;
    #pragma unroll
    for (int k=0;k<7;k++){
      float2 q = p01[base+k];
      s0 += w[k]*q.x;
      s1 += w[k]*q.y;
      s2 += w[k]*p2[base+k];
    }
    t01[i] = make_float2(s0,s1);
    t2[i]  = s2;
  }
  __syncthreads();

  // D: col pass + min eigenvalue, 36x36
  for (int i=tid; i<1296; i+=1024){
    int iy=i/36, x=i%36;
    float b0=0.f,b1=0.f,b2=0.f;
    #pragma unroll
    for (int k=0;k<7;k++){
      int o=(iy+k)*36+x;
      float2 q = t01[o];
      b0 += w[k]*q.x;
      b1 += w[k]*q.y;
      b2 += w[k]*t2[o];
    }
    float det=b0*b1-b2*b2;
    float tr=b0+b1;
    float r=0.5f*(tr - sqrtf(fabsf(tr*tr - 4.0f*det)));
    int ry=ty0-2+iy, rx=tx0-2+x;
    resp[i] = (ry>=0 && ry<HW && rx>=0 && rx<HW) ? r : NEG;
  }
  __syncthreads();

  // E0: row max of 5, 36x32
  for (int i=tid;i<1152;i+=1024){
    int iy=i/32, x=i%32;
    int base=iy*36+x;
    float m = fmaxf(fmaxf(fmaxf(resp[base],resp[base+1]),fmaxf(resp[base+2],resp[base+3])),resp[base+4]);
    rm[i]=m;
  }
  __syncthreads();
  // E1: col max of 5 -> NMS
  {
    float v = resp[(oy+2)*36 + ox+2];
    float m = fmaxf(fmaxf(fmaxf(rm[oy*32+ox],rm[(oy+1)*32+ox]),
                          fmaxf(rm[(oy+2)*32+ox],rm[(oy+3)*32+ox])),rm[(oy+4)*32+ox]);
    sv[oy*32+ox] = (v==m) ? v : 0.0f;
  }
  __syncthreads();
  // E2: per-8x8-block max
  if ((oy&7)==0 && (ox&7)==0){
    float bv = sv[oy*32+ox];
    int   bp = (ty0+oy)*HW + (tx0+ox);
    for (int i=0;i<8;i++)
      for (int j=0;j<8;j++){
        float q = sv[(oy+i)*32 + ox+j];
        if (q > bv){ bv=q; bp=(ty0+oy+i)*HW + (tx0+ox+j); }
      }
    int bidx = b*4096 + ((ty0+oy)>>3)*64 + ((tx0+ox)>>3);
    g_bval[bidx]=bv; g_bpos[bidx]=bp;
  }
}

// ============ K2: radix-select (500th) + select + second NMS + deterministic compaction ============
__global__ __launch_bounds__(1024) void k2(){
  const int img = blockIdx.x, tid = threadIdx.x;
  __shared__ float fv[4096];
  __shared__ int   pos[4096];
  __shared__ unsigned hist[256];
  __shared__ int cnts[1024];
  __shared__ unsigned s_prefix;
  __shared__ int s_k;
  for (int i=tid;i<4096;i+=1024){
    fv[i]=g_bval[img*4096+i];
    pos[i]=g_bpos[img*4096+i];
  }
  if (tid==0){ s_prefix=0u; s_k=500; }
  __syncthreads();

  // 4 x 8-bit MSB-first radix select
  for (int pass=0; pass<4; pass++){
    int shift = 24 - 8*pass;
    unsigned hi_mask = (pass==0) ? 0u : (0xFFFFFFFFu << (shift+8));
    if (tid < 256) hist[tid]=0u;
    __syncthreads();
    unsigned pfx = s_prefix;
    int kk = s_k;
    for (int i=tid;i<4096;i+=1024){
      unsigned bits = __float_as_uint(fv[i]);
      unsigned u = (bits & 0x80000000u) ? ~bits : (bits | 0x80000000u);
      if ((u & hi_mask) == pfx) atomicAdd(&hist[(u>>shift)&255u], 1u);
    }
    __syncthreads();
    // inclusive suffix scan of hist: hist[d] := count(digit >= d)
    for (int off=1; off<256; off<<=1){
      unsigned v=0u;
      if (tid<256) v = (tid+off<256) ? hist[tid+off] : 0u;
      __syncthreads();
      if (tid<256) hist[tid] += v;
      __syncthreads();
    }
    if (tid<256){
      unsigned ge = hist[tid];
      unsigned gt = (tid<255) ? hist[tid+1] : 0u;
      if (ge >= (unsigned)kk && gt < (unsigned)kk){
        s_prefix = pfx | ((unsigned)tid << shift);
        s_k = kk - (int)gt;
      }
    }
    __syncthreads();
  }
  unsigned u = s_prefix;
  unsigned tbits = (u & 0x80000000u) ? (u ^ 0x80000000u) : ~u;
  float thr = __uint_as_float(tbits);

  // select + 3x3-block-neighborhood second NMS; thread t owns slots 4t..4t+3
  int srv[4];
  int mycnt = 0;
  #pragma unroll
  for (int j=0;j<4;j++){
    int i = tid*4 + j;
    float v = fv[i];
    int s = -1;
    if (v>0.0f && v>=thr){
      int by=i>>6, bx=i&63;
      int p = pos[i];
      int y=p>>9, x=p&511;
      bool ok = true;
      #pragma unroll
      for (int dby=-1;dby<=1;dby++)
        #pragma unroll
        for (int dbx=-1;dbx<=1;dbx++){
          if (dby==0 && dbx==0) continue;
          int nby=by+dby, nbx=bx+dbx;
          if (nby<0||nby>63||nbx<0||nbx>63) continue;
          int n = nby*64+nbx;
          float nv = fv[n];
          if (nv>v && nv>=thr){
            int np = pos[n];
            int ny=np>>9, nx=np&511;
            if (abs(ny-y)<=2 && abs(nx-x)<=2) ok=false;
          }
        }
      s = ok ? p : -1;
    }
    srv[j]=s;
    mycnt += (s>=0);
  }
  // stable compaction: inclusive scan of per-thread counts
  cnts[tid]=mycnt;
  __syncthreads();
  for (int off=1; off<1024; off<<=1){
    int v = (tid>=off) ? cnts[tid-off] : 0;
    __syncthreads();
    cnts[tid] += v;
    __syncthreads();
  }
  int offs = cnts[tid] - mycnt;
  #pragma unroll
  for (int j=0;j<4;j++){
    if (srv[j]>=0){
      if (offs < LCAP) g_list[img*LCAP + offs] = srv[j];
      offs++;
    }
  }
  if (tid==1023){
    int tot = cnts[1023];
    g_cnt[img] = tot > LCAP ? LCAP : tot;
  }
}

// ============ K4: one warp per compacted survivor slot ============
__global__ __launch_bounds__(1024) void k4(const float* __restrict__ scores){
  const int w32 = blockIdx.x*32 + (threadIdx.x>>5);   // warp id in [0, NB*LCAP)
  const int lane = threadIdx.x & 31;
  const int img = w32 / LCAP;
  const int idx = w32 - img*LCAP;
  float acc = 0.0f;
  if (idx < g_cnt[img]){
    const int s = g_list[w32];
    const float* sp = scores + (size_t)img*HW*HW;
    float wk[7]; gw7(wk);
    const int y = s>>9, x = s&511;
    #pragma unroll
    for (int t=lane; t<49; t+=32){
      int ky=t/7, kx=t-ky*7;
      int yy = refl512(y+ky-3);
      int xx = refl512(x+kx-3);
      float p = sp[yy*HW+xx];
      float lp = fmaxf(logf(p), -100.0f);
      float l1 = fmaxf(log1pf(-p), -100.0f);
      acc += wk[ky]*wk[kx]*(lp - l1);
    }
  }
  #pragma unroll
  for (int off=16;off;off>>=1) acc += __shfl_down_sync(0xffffffffu, acc, off);
  if (lane==0) g_corr[w32] = acc;
}

// ============ K5: deterministic final reduction ============
__global__ __launch_bounds__(1024) void k5(float* __restrict__ out){
  __shared__ double sb[1024], sr[1024], sx[1024];
  const int t = threadIdx.x;
  double b=0.0, r=0.0, c=0.0;
  for (int i=t;i<4096;i+=1024){ b += g_pb[i]; r += g_pr[i]; }
  for (int i=t;i<NB*LCAP;i+=1024) c += (double)g_corr[i];
  sb[t]=b; sr[t]=r; sx[t]=c; __syncthreads();
  for (int s=512;s;s>>=1){
    if (t<s){ sb[t]+=sb[t+s]; sr[t]+=sr[t+s]; sx[t]+=sx[t+s]; }
    __syncthreads();
  }
  if (t==0){
    double n = (double)NPIX;
    out[0] = (float)((sb[0]-sx[0])/n + (sr[0]/n)*10.0);
  }
}

// ---------------- launch ----------------
extern "C" void kernel_launch(void* const* d_in, const int* in_sizes, int n_in,
                              void* d_out, int out_size){
  const float* scores = (const float*)d_in[0];
  const float* imgs   = (const float*)d_in[1];
  if (in_sizes[0] != NB*1*HW*HW){
    const float* tmp = scores; scores = imgs; imgs = tmp;
  }
  dim3 blk(32,32), grd(16,16,NB);
  kmain<<<grd, blk>>>(imgs, scores);
  k2<<<NB, 1024>>>();
  k4<<<(NB*LCAP)/32, 1024>>>(scores);
  k5<<<1, 1024>>>((float*)d_out);
}

// round 6
// speedup vs baseline: 1.8332x; 1.0557x over previous
#include <cuda_runtime.h>
#include <math.h>

#define NB 16
#define HW 512
#define NPIX (NB*HW*HW)
#define LCAP 768
#define K4CTAS (NB*LCAP/32)   // 384

// ---------------- device scratch ----------------
__device__ float    g_bval[NB*4096];
__device__ int      g_bpos[NB*4096];
__device__ int      g_list[NB*LCAP];
__device__ int      g_cnt[NB];
__device__ double   g_pb[4096];
__device__ double   g_pr[4096];
__device__ double   g_pc[K4CTAS];
__device__ unsigned g_arrive;   // zero-initialized; reset by last CTA each call

__device__ __forceinline__ int refl512(int i){ return i<0 ? -i : (i>511 ? 1022-i : i); }
__device__ __forceinline__ int clamp512(int i){ return i<0?0:(i>511?511:i); }

__device__ __forceinline__ void gw7(float* w){
  float e0=expf(-4.5f), e1=expf(-2.0f), e2=expf(-0.5f);
  float s=1.0f+2.0f*(e0+e1+e2);
  w[0]=e0/s; w[1]=e1/s; w[2]=e2/s; w[3]=1.0f/s; w[4]=w[2]; w[5]=w[1]; w[6]=w[0];
}

// ============ KMAIN: [scores lap/bce/reg] + [gray->sobel->ST->gauss7->mineig->NMS->blockmax] ============
__global__ __launch_bounds__(1024) void kmain(const float* __restrict__ imgs,
                                              const float* __restrict__ scores){
  const int b = blockIdx.z;
  const int ty0 = blockIdx.y*32, tx0 = blockIdx.x*32;
  __shared__ __align__(16) float buf[11764];
  const int tid = threadIdx.y*32 + threadIdx.x;
  const int oy = threadIdx.y, ox = threadIdx.x;
  const float NEG = __int_as_float(0xff800000u);

  // ---------- phase 0: scores tile -> laplacian + reg + base bce ----------
  {
    float* sc = buf;            // 36x36
    float* rs = buf + 1296;     // 36x32
    float* rb = buf + 2448;     // 32
    float* rr2= buf + 2480;     // 32
    const float* sp = scores + (size_t)b*HW*HW;
    for (int i=tid;i<1296;i+=1024){
      int iy=i/36, ix=i%36;
      sc[i] = sp[refl512(ty0-2+iy)*HW + refl512(tx0-2+ix)];
    }
    __syncthreads();
    for (int i=tid;i<1152;i+=1024){
      int iy=i/32, x=i%32;
      int base=iy*36+x;
      rs[i] = sc[base]+sc[base+1]+sc[base+2]+sc[base+3]+sc[base+4];
    }
    __syncthreads();
    float S = rs[oy*32+ox]+rs[(oy+1)*32+ox]+rs[(oy+2)*32+ox]+rs[(oy+3)*32+ox]+rs[(oy+4)*32+ox];
    float p = sc[(oy+2)*36 + ox+2];
    float lap = (S - 25.0f*p) * (1.0f/48.0f);
    float reg = p * expf(-lap);
    float bce0 = -fmaxf(log1pf(-p), -100.0f);
    float v1=bce0, v2=reg;
    #pragma unroll
    for (int off=16;off;off>>=1){
      v1 += __shfl_down_sync(0xffffffffu, v1, off);
      v2 += __shfl_down_sync(0xffffffffu, v2, off);
    }
    if ((tid&31)==0){ rb[tid>>5]=v1; rr2[tid>>5]=v2; }
    __syncthreads();
    if (tid<32){
      float a1=rb[tid], a2=rr2[tid];
      #pragma unroll
      for (int off=16;off;off>>=1){
        a1 += __shfl_down_sync(0xffffffffu, a1, off);
        a2 += __shfl_down_sync(0xffffffffu, a2, off);
      }
      if (tid==0){
        int bid = (blockIdx.z*16 + blockIdx.y)*16 + blockIdx.x;
        g_pb[bid]=(double)a1; g_pr[bid]=(double)a2;
      }
    }
  }

  // ---------- GFTT pipeline ----------
  float2* p01 = (float2*)buf;          // 42x42 float2 = [0, 3528)
  float*  p2  = buf + 3528;            // 42x42 = [3528, 5292)
  float2* t01 = (float2*)(buf + 5292); // 42x36 float2 = [5292, 8316)
  float*  t2  = buf + 8316;            // 42x36 = [8316, 9828)
  float*  sg  = buf + 9828;            // 44x44 = 1936
  float*  resp= buf + 9828;            // 36x36 (aliases sg, after B)
  float*  rm  = buf;                   // 36x32 rowmax (aliases p01, after D)
  float*  sv  = buf + 1152;            // 32x32

  const float* rr = imgs + (size_t)b*3*HW*HW;
  const float* gg = rr + HW*HW;
  const float* bb = gg + HW*HW;

  // A: gray with replicate clamp, 44x44  (barrier below also protects phase0 smem)
  for (int i=tid; i<1936; i+=1024){
    int iy=i/44, ix=i%44;
    int gy=clamp512(ty0-6+iy), gx=clamp512(tx0-6+ix);
    int o=gy*HW+gx;
    sg[i] = 0.299f*rr[o] + 0.587f*gg[o] + 0.114f*bb[o];
  }
  __syncthreads();

  // B: gradient products at reflected coords, 42x42
  for (int i=tid; i<1764; i+=1024){
    int iy=i/42, ix=i%42;
    int qy=refl512(ty0-5+iy), qx=refl512(tx0-5+ix);
    int ly=qy-ty0+6, lx=qx-tx0+6;
    const float* c0=&sg[(ly-1)*44+lx];
    const float* c1=&sg[ ly   *44+lx];
    const float* c2=&sg[(ly+1)*44+lx];
    float a=c0[-1], b_=c0[0], c=c0[1];
    float d=c1[-1],            e=c1[1];
    float f=c2[-1], h=c2[0],  k=c2[1];
    float dx=(c-a+2.0f*(e-d)+k-f)*0.125f;
    float dy=(f-a+2.0f*(h-b_)+k-c)*0.125f;
    p01[i] = make_float2(dx*dx, dy*dy);
    p2[i]  = dx*dy;
  }
  __syncthreads();

  float w[7]; gw7(w);

  // C: row blur, 42 rows x 36 cols; 2 adjacent x per thread (8 taps -> 2 outputs)
  for (int i=tid; i<756; i+=1024){
    int iy=i/18, j=i%18;
    int x0=2*j;
    int base=iy*42+x0;
    float a0=0.f,a1=0.f,a2=0.f, b0=0.f,b1=0.f,b2=0.f;
    #pragma unroll
    for (int k=0;k<8;k++){
      float2 q = p01[base+k];
      float  r = p2[base+k];
      if (k<7){ a0+=w[k]*q.x; a1+=w[k]*q.y; a2+=w[k]*r; }
      if (k>0){ b0+=w[k-1]*q.x; b1+=w[k-1]*q.y; b2+=w[k-1]*r; }
    }
    int o = iy*36+x0;
    t01[o]   = make_float2(a0,a1); t2[o]   = a2;
    t01[o+1] = make_float2(b0,b1); t2[o+1] = b2;
  }
  __syncthreads();

  // D: col blur + min eigenvalue, 36x36; 2 adjacent y per thread (8 rows -> 2 outputs)
  for (int i=tid; i<648; i+=1024){
    int row=i/36, x=i%36;
    int iy=2*row;
    float a0=0.f,a1=0.f,a2=0.f, b0=0.f,b1=0.f,b2=0.f;
    #pragma unroll
    for (int k=0;k<8;k++){
      int o=(iy+k)*36+x;
      float2 q = t01[o];
      float  r = t2[o];
      if (k<7){ a0+=w[k]*q.x; a1+=w[k]*q.y; a2+=w[k]*r; }
      if (k>0){ b0+=w[k-1]*q.x; b1+=w[k-1]*q.y; b2+=w[k-1]*r; }
    }
    {
      float det=a0*a1-a2*a2, tr=a0+a1;
      float r0=0.5f*(tr - sqrtf(fabsf(tr*tr - 4.0f*det)));
      int ry=ty0-2+iy, rx=tx0-2+x;
      resp[iy*36+x] = (ry>=0 && ry<HW && rx>=0 && rx<HW) ? r0 : NEG;
    }
    {
      float det=b0*b1-b2*b2, tr=b0+b1;
      float r1=0.5f*(tr - sqrtf(fabsf(tr*tr - 4.0f*det)));
      int ry=ty0-1+iy, rx=tx0-2+x;
      resp[(iy+1)*36+x] = (ry>=0 && ry<HW && rx>=0 && rx<HW) ? r1 : NEG;
    }
  }
  __syncthreads();

  // E0: row max of 5, 36x32
  for (int i=tid;i<1152;i+=1024){
    int iy=i/32, x=i%32;
    int base=iy*36+x;
    float m = fmaxf(fmaxf(fmaxf(resp[base],resp[base+1]),fmaxf(resp[base+2],resp[base+3])),resp[base+4]);
    rm[i]=m;
  }
  __syncthreads();
  // E1: col max -> NMS
  {
    float v = resp[(oy+2)*36 + ox+2];
    float m = fmaxf(fmaxf(fmaxf(rm[oy*32+ox],rm[(oy+1)*32+ox]),
                          fmaxf(rm[(oy+2)*32+ox],rm[(oy+3)*32+ox])),rm[(oy+4)*32+ox]);
    sv[oy*32+ox] = (v==m) ? v : 0.0f;
  }
  __syncthreads();
  // E2: per-8x8-block max
  if ((oy&7)==0 && (ox&7)==0){
    float bv = sv[oy*32+ox];
    int   bp = (ty0+oy)*HW + (tx0+ox);
    for (int i=0;i<8;i++)
      for (int j=0;j<8;j++){
        float q = sv[(oy+i)*32 + ox+j];
        if (q > bv){ bv=q; bp=(ty0+oy+i)*HW + (tx0+ox+j); }
      }
    int bidx = b*4096 + ((ty0+oy)>>3)*64 + ((tx0+ox)>>3);
    g_bval[bidx]=bv; g_bpos[bidx]=bp;
  }
}

// ============ K2: radix-select + select + second NMS + deterministic compaction ============
__global__ __launch_bounds__(1024) void k2(){
  const int img = blockIdx.x, tid = threadIdx.x;
  const int lane = tid&31, wid = tid>>5;
  __shared__ float fv[4096];
  __shared__ int   pos[4096];
  __shared__ unsigned hist[256];
  __shared__ int wsum[32];
  __shared__ unsigned s_prefix;
  __shared__ int s_k;
  for (int i=tid;i<4096;i+=1024){
    fv[i]=g_bval[img*4096+i];
    pos[i]=g_bpos[img*4096+i];
  }
  if (tid==0){ s_prefix=0u; s_k=500; }
  __syncthreads();

  for (int pass=0; pass<4; pass++){
    int shift = 24 - 8*pass;
    unsigned hi_mask = (pass==0) ? 0u : (0xFFFFFFFFu << (shift+8));
    if (tid < 256) hist[tid]=0u;
    __syncthreads();
    unsigned pfx = s_prefix;
    int kk = s_k;
    for (int i=tid;i<4096;i+=1024){
      unsigned bits = __float_as_uint(fv[i]);
      unsigned u = (bits & 0x80000000u) ? ~bits : (bits | 0x80000000u);
      if ((u & hi_mask) == pfx) atomicAdd(&hist[(u>>shift)&255u], 1u);
    }
    __syncthreads();
    // single-warp suffix scan: hist[d] := count(digit >= d)
    if (tid<32){
      int base=tid*8;
      unsigned c[8];
      #pragma unroll
      for (int j=0;j<8;j++) c[j]=hist[base+j];
      unsigned tot=0;
      #pragma unroll
      for (int j=0;j<8;j++) tot+=c[j];
      unsigned suf=tot;
      #pragma unroll
      for (int off=1;off<32;off<<=1){
        unsigned n=__shfl_down_sync(0xffffffffu, suf, off);
        if (lane+off<32) suf+=n;
      }
      unsigned run = suf - tot;           // sum over chunks > this one
      #pragma unroll
      for (int j=7;j>=0;j--){ run += c[j]; hist[base+j]=run; }
    }
    __syncthreads();
    if (tid<256){
      unsigned ge = hist[tid];
      unsigned gt = (tid<255) ? hist[tid+1] : 0u;
      if (ge >= (unsigned)kk && gt < (unsigned)kk){
        s_prefix = pfx | ((unsigned)tid << shift);
        s_k = kk - (int)gt;
      }
    }
    __syncthreads();
  }
  unsigned u = s_prefix;
  unsigned tbits = (u & 0x80000000u) ? (u ^ 0x80000000u) : ~u;
  float thr = __uint_as_float(tbits);

  // select + 3x3-block second NMS; thread t owns slots 4t..4t+3
  int srv[4];
  int mycnt = 0;
  #pragma unroll
  for (int j=0;j<4;j++){
    int i = tid*4 + j;
    float v = fv[i];
    int s = -1;
    if (v>0.0f && v>=thr){
      int by=i>>6, bx=i&63;
      int p = pos[i];
      int y=p>>9, x=p&511;
      bool ok = true;
      #pragma unroll
      for (int dby=-1;dby<=1;dby++)
        #pragma unroll
        for (int dbx=-1;dbx<=1;dbx++){
          if (dby==0 && dbx==0) continue;
          int nby=by+dby, nbx=bx+dbx;
          if (nby<0||nby>63||nbx<0||nbx>63) continue;
          int n = nby*64+nbx;
          float nv = fv[n];
          if (nv>v && nv>=thr){
            int np = pos[n];
            int ny=np>>9, nx=np&511;
            if (abs(ny-y)<=2 && abs(nx-x)<=2) ok=false;
          }
        }
      s = ok ? p : -1;
    }
    srv[j]=s;
    mycnt += (s>=0);
  }
  // stable compaction via warp-shuffle scans
  int v = mycnt;
  #pragma unroll
  for (int off=1;off<32;off<<=1){
    int n=__shfl_up_sync(0xffffffffu, v, off);
    if (lane>=off) v+=n;
  }
  if (lane==31) wsum[wid]=v;
  __syncthreads();
  if (wid==0){
    int s=wsum[lane];
    #pragma unroll
    for (int off=1;off<32;off<<=1){
      int n=__shfl_up_sync(0xffffffffu, s, off);
      if (lane>=off) s+=n;
    }
    wsum[lane]=s;
  }
  __syncthreads();
  int offs = (wid ? wsum[wid-1] : 0) + v - mycnt;
  #pragma unroll
  for (int j=0;j<4;j++){
    if (srv[j]>=0){
      if (offs < LCAP) g_list[img*LCAP + offs] = srv[j];
      offs++;
    }
  }
  if (tid==1023){
    int tot = wsum[31];
    g_cnt[img] = tot > LCAP ? LCAP : tot;
  }
}

// ============ K4: warp-per-survivor correction + CTA partials + fused final reduction ============
__global__ __launch_bounds__(1024) void k4(const float* __restrict__ scores,
                                           float* __restrict__ out){
  const int tid = threadIdx.x;
  const int wid = tid>>5, lane = tid&31;
  const int w32 = blockIdx.x*32 + wid;
  const int img = w32 / LCAP;
  const int idx = w32 - img*LCAP;
  __shared__ float wsumf[32];
  __shared__ bool isLast;
  float acc = 0.0f;
  if (idx < g_cnt[img]){
    const int s = g_list[w32];
    const float* sp = scores + (size_t)img*HW*HW;
    float wk[7]; gw7(wk);
    const int y = s>>9, x = s&511;
    #pragma unroll
    for (int t=lane; t<49; t+=32){
      int ky=t/7, kx=t-ky*7;
      int yy = refl512(y+ky-3);
      int xx = refl512(x+kx-3);
      float p = sp[yy*HW+xx];
      float lp = fmaxf(logf(p), -100.0f);
      float l1 = fmaxf(log1pf(-p), -100.0f);
      acc += wk[ky]*wk[kx]*(lp - l1);
    }
  }
  #pragma unroll
  for (int off=16;off;off>>=1) acc += __shfl_down_sync(0xffffffffu, acc, off);
  if (lane==0) wsumf[wid]=acc;
  __syncthreads();
  if (tid==0){
    double s=0.0;
    for (int i=0;i<32;i++) s += (double)wsumf[i];
    g_pc[blockIdx.x]=s;
    __threadfence();
    unsigned t = atomicAdd(&g_arrive, 1u);
    isLast = (t == (unsigned)(gridDim.x-1));
  }
  __syncthreads();
  if (!isLast) return;

  // ----- last CTA: deterministic final reduction -----
  __shared__ double sb[1024], sr[1024];
  double bsum=0.0, rsum=0.0;
  for (int i=tid;i<4096;i+=1024){ bsum += g_pb[i]; rsum += g_pr[i]; }
  double csum = (tid<K4CTAS) ? g_pc[tid] : 0.0;
  sb[tid]=bsum; sr[tid]=rsum+0.0;
  __shared__ double sx[1024];
  sx[tid]=csum;
  __syncthreads();
  for (int s=512;s;s>>=1){
    if (tid<s){ sb[tid]+=sb[tid+s]; sr[tid]+=sr[tid+s]; sx[tid]+=sx[tid+s]; }
    __syncthreads();
  }
  if (tid==0){
    double n = (double)NPIX;
    out[0] = (float)((sb[0]-sx[0])/n + (sr[0]/n)*10.0);
    g_arrive = 0u;   // reset for next graph replay
  }
}

// ---------------- launch ----------------
extern "C" void kernel_launch(void* const* d_in, const int* in_sizes, int n_in,
                              void* d_out, int out_size){
  const float* scores = (const float*)d_in[0];
  const float* imgs   = (const float*)d_in[1];
  if (in_sizes[0] != NB*1*HW*HW){
    const float* tmp = scores; scores = imgs; imgs = tmp;
  }
  dim3 blk(32,32), grd(16,16,NB);
  kmain<<<grd, blk>>>(imgs, scores);
  k2<<<NB, 1024>>>();
  k4<<<K4CTAS, 1024>>>(scores, (float*)d_out);
}